// round 2
// baseline (speedup 1.0000x reference)
#include <cuda_runtime.h>
#include <cstdint>

// MeanAggregator: out[b, :] = mean_k features[neigh_idx[b, k], :]
// B=16384, K=15, U=19997, D=256
// neigh_idx is int32 on device (JAX x64-disabled downcasts the int64).
//
// 64 lanes per row (each lane owns a float4 -> 64*4 = 256 = D),
// 4 rows per 256-thread block. Indices staged through shared memory.
// Fully unrolled K loop -> 15 independent LDG.128 in flight per thread.

#define K_NEIGH 15
#define D_DIM 256
#define LANES_PER_ROW 64
#define ROWS_PER_BLOCK 4

__global__ __launch_bounds__(LANES_PER_ROW * ROWS_PER_BLOCK)
void mean_agg_kernel(const int* __restrict__ neigh_idx,
                     const float* __restrict__ features,
                     float* __restrict__ out,
                     int B)
{
    const int ty   = threadIdx.y;
    const int lane = threadIdx.x;                 // 0..63
    const int row  = blockIdx.x * ROWS_PER_BLOCK + ty;

    __shared__ int sidx[ROWS_PER_BLOCK][K_NEIGH];

    if (row < B && lane < K_NEIGH) {
        sidx[ty][lane] = neigh_idx[row * K_NEIGH + lane];
    }
    __syncthreads();

    if (row >= B) return;

    float4 acc = make_float4(0.f, 0.f, 0.f, 0.f);

    #pragma unroll
    for (int k = 0; k < K_NEIGH; ++k) {
        const size_t off = (size_t)sidx[ty][k] * D_DIM + lane * 4;
        const float4 v = *reinterpret_cast<const float4*>(features + off);
        acc.x += v.x; acc.y += v.y; acc.z += v.z; acc.w += v.w;
    }

    const float inv = 1.0f / (float)K_NEIGH;
    acc.x *= inv; acc.y *= inv; acc.z *= inv; acc.w *= inv;

    *reinterpret_cast<float4*>(out + (size_t)row * D_DIM + lane * 4) = acc;
}

extern "C" void kernel_launch(void* const* d_in, const int* in_sizes, int n_in,
                              void* d_out, int out_size)
{
    // Identify inputs by element count: idx has B*K elements, features U*D.
    int idx_slot = 0, feat_slot = 1;
    if (n_in >= 2 && in_sizes[0] > in_sizes[1]) { idx_slot = 1; feat_slot = 0; }

    const int*   neigh_idx = (const int*)d_in[idx_slot];     // [B, K] int32
    const float* features  = (const float*)d_in[feat_slot];  // [U, D] fp32
    float*       out       = (float*)d_out;                  // [B, D] fp32

    const int B = in_sizes[idx_slot] / K_NEIGH;

    dim3 block(LANES_PER_ROW, ROWS_PER_BLOCK);
    dim3 grid((B + ROWS_PER_BLOCK - 1) / ROWS_PER_BLOCK);
    mean_agg_kernel<<<grid, block>>>(neigh_idx, features, out, B);
}